// round 14
// baseline (speedup 1.0000x reference)
#include <cuda_runtime.h>
#include <cuda_bf16.h>
#include <cstdint>
#include <math.h>

#define H1 56
#define W1 56
#define BB 16
#define NN 32
#define CC 512
#define RH 60
#define RW 60
#define OH 224
#define OW 224
#define KS 33
#define KC 64

// ---------------- scratch (device globals; no allocation allowed) ----------
__device__ __nv_bfloat16 g_Eb[H1 * W1 * BB * CC];     // 51.4 MB
__device__ float g_xn[H1 * W1 * BB];
__device__ float g_best[H1 * W1 * BB];                // min dsq, via atomicMin(int)
__device__ float g_pix56[BB * H1 * W1];
__device__ float g_tmp[BB * OH * H1];                 // W·P stage (16x224x56)
__device__ float g_W[OH * H1];                        // fused resize+blur matrix
__device__ float g_Wt[H1 * OH];                       // its transpose

// ---------------- W matrix only (1 block, 224 threads) ---------------------
__global__ void k_initW() {
    int i = threadIdx.x;
    float gwv[KS], ssum = 0.f;
#pragma unroll
    for (int t = 0; t < KS; t++) {
        float x = (t - (KS - 1) / 2) * 0.25f;
        gwv[t] = expf(-0.5f * x * x);
        ssum += gwv[t];
    }
    float acc[H1];
#pragma unroll
    for (int k = 0; k < H1; k++) acc[k] = 0.f;
    for (int t = 0; t < KS; t++) {
        int yy = i + t - 16;
        yy = yy < 0 ? -yy : (yy > 223 ? 446 - yy : yy);
        float uy = fminf(fmaxf((yy + 0.5f) * 0.25f - 0.5f, 0.f), 55.f);
        int y0 = (int)uy;
        float fy = uy - y0;
        int y1 = min(y0 + 1, H1 - 1);
        float g = gwv[t] / ssum;
        acc[y0] += g * (1.f - fy);
        acc[y1] += g * fy;
    }
    for (int k = 0; k < H1; k++) {
        g_W[i * H1 + k] = acc[k];
        g_Wt[k * OH + i] = acc[k];
    }
}

// ---------------- fp32 -> bf16 conversion + norms + best/out init ----------
__global__ void k_convert_e(const float* __restrict__ src, float* __restrict__ out) {
    int gi = blockIdx.x * blockDim.x + threadIdx.x;
    if (gi < H1 * W1 * BB) g_best[gi] = __int_as_float(0x7f800000);
    if (gi < BB) out[gi] = 0.f;

    int gw = gi >> 5;
    int lane = threadIdx.x & 31;
    if (gw >= H1 * W1 * BB) return;
    const float4* s = (const float4*)(src + (size_t)gw * CC);
    uint2* d = (uint2*)(g_Eb + (size_t)gw * CC);
    float acc = 0.f;
#pragma unroll
    for (int it = 0; it < 4; it++) {
        float4 v = s[it * 32 + lane];
        acc += v.x * v.x + v.y * v.y + v.z * v.z + v.w * v.w;
        __nv_bfloat162 lo = __floats2bfloat162_rn(v.x, v.y);
        __nv_bfloat162 hi = __floats2bfloat162_rn(v.z, v.w);
        uint2 o;
        o.x = *(uint32_t*)&lo;
        o.y = *(uint32_t*)&hi;
        d[it * 32 + lane] = o;
    }
#pragma unroll
    for (int off = 16; off; off >>= 1) acc += __shfl_xor_sync(~0u, acc, off);
    if (lane == 0) g_xn[gw] = acc;
}

// ---------------- main distance kernel: one CTA per PAIR of tiles ----------
__device__ __forceinline__ void mma16816(float* d, uint32_t a0, uint32_t a1,
                                         uint32_t a2, uint32_t a3,
                                         uint32_t b0, uint32_t b1) {
    asm volatile(
        "mma.sync.aligned.m16n8k16.row.col.f32.bf16.bf16.f32 "
        "{%0,%1,%2,%3}, {%4,%5,%6,%7}, {%8,%9}, {%0,%1,%2,%3};\n"
        : "+f"(d[0]), "+f"(d[1]), "+f"(d[2]), "+f"(d[3])
        : "r"(a0), "r"(a1), "r"(a2), "r"(a3), "r"(b0), "r"(b1));
}

__device__ __forceinline__ void ldsm_x4(uint32_t& r0, uint32_t& r1,
                                        uint32_t& r2, uint32_t& r3, uint32_t addr) {
    asm volatile("ldmatrix.sync.aligned.m8n8.x4.shared.b16 {%0,%1,%2,%3}, [%4];"
                 : "=r"(r0), "=r"(r1), "=r"(r2), "=r"(r3) : "r"(addr));
}

__device__ __forceinline__ void cp_async16(uint32_t dst, const void* src) {
    asm volatile("cp.async.cg.shared.global [%0], [%1], 16;" ::"r"(dst), "l"(src));
}

__device__ __forceinline__ uint32_t sw128(uint32_t off) {
    return off ^ ((off >> 3) & 0x70);
}

// smem layout (bytes), fused 2-tile version:
#define A_STAGE_B 61440
#define B_STAGE_B 8192
#define SM_A   0
#define SM_B   122880
#define SM_XN  139264          // 480 floats
#define SM_YN  141184          // 64 floats
#define SM_Q   141440          // 32 ints
#define SM_TOT 141568

#define NWARP 16
#define NTHR  512

__global__ void __launch_bounds__(NTHR, 1) k_dist(const float* __restrict__ mem) {
    extern __shared__ char smem[];
    float* xn_s = (float*)(smem + SM_XN);
    float* yn_s = (float*)(smem + SM_YN);
    int* qoff_s = (int*)(smem + SM_Q);
    const uint32_t sm_u32 = (uint32_t)__cvta_generic_to_shared(smem);
    const uint32_t smA_u32 = sm_u32 + SM_A;
    const uint32_t smB_u32 = sm_u32 + SM_B;

    const int r = blockIdx.x / (RW / 2);
    const int s0 = (blockIdx.x % (RW / 2)) * 2;
    const int t0 = r * RW + s0;                       // tiles t0, t0+1
    const int tid = threadIdx.x;
    const int wid = tid >> 5, lane = tid & 31;

    if (tid < 30) {
        int dh = tid / 6, dw = tid % 6;
        int h = r - 4 + dh, w = s0 - 4 + dw;
        qoff_s[tid] = (h >= 0 && h < H1 && w >= 0 && w < W1) ? (h * W1 + w) * BB : -1;
    }
    __syncthreads();
    if (tid < 480) {
        int q = qoff_s[tid >> 4];
        xn_s[tid] = (q >= 0) ? g_xn[q + (tid & 15)] : 0.f;
    }

    // warp's valid slots (warp-uniform): up to 2, with per-tile masks
    int sp[2];
    bool m0[2] = {false, false}, m1[2] = {false, false};
    int nsl = 0;
#pragma unroll
    for (int p = wid; p < 30; p += NWARP)
        if (qoff_s[p] >= 0) {
            sp[nsl] = p;
            int dw = p % 6;
            m0[nsl] = (dw <= 4);                      // slot feeds tile0
            m1[nsl] = (dw >= 1);                      // slot feeds tile1
            nsl++;
        }
    const bool need0 = m0[0] || m0[1];                // warp needs tile0 B rows
    const bool need1 = m1[0] || m1[1];

    float acc[2][8][4];
#pragma unroll
    for (int a = 0; a < 2; a++)
#pragma unroll
        for (int g = 0; g < 8; g++)
#pragma unroll
            for (int c = 0; c < 4; c++) acc[a][g][c] = 0.f;

    // ---- hoisted A load addressing (480 rows, 8 slot-groups) ---------------
    const int seg = tid & 7;
    const int rowin = (tid >> 3) & 15;
    const int slot0 = tid >> 7;                       // 0..3
    const uint32_t adst0 = slot0 * 2048 + sw128(rowin * 128 + seg * 16);

    int aoffq[8];
#pragma unroll
    for (int i = 0; i < 8; i++) {
        int slot = slot0 + i * 4;
        int v = -1;
        if (slot < 30) {
            int q = qoff_s[slot];
            if (q >= 0) v = (q + rowin) * (CC / 8) + seg;
        }
        aoffq[i] = v;
    }
    const uint4* EbV = (const uint4*)g_Eb;

    auto load_stage = [&](int kc, int buf) {
        const uint32_t abase = smA_u32 + buf * A_STAGE_B + adst0;
        const int kadd = kc * 8;
#pragma unroll
        for (int i = 0; i < 8; i++) {
            if (aoffq[i] >= 0)
                cp_async16(abase + i * 8192, EbV + aoffq[i] + kadd);
        }
        asm volatile("cp.async.commit_group;");
    };

    // ---- B path: 64 rows fp32 -> bf16 (2 float4 per thread per stage) ------
    const int brow = tid >> 3;                        // 0..63
    const int j0 = (tid & 7) * 2;                     // even float4 index 0..14
    const float4* bsrcf =
        (const float4*)(mem + ((size_t)(t0 + (brow >> 5)) * NN + (brow & 31)) * CC) + j0;
    const uint32_t bdst = smB_u32 + sw128(brow * 128 + j0 * 8);
    float ynacc = 0.f;

    auto b_convert_store = [&](float4 v0, float4 v1, int buf) {
        ynacc += v0.x * v0.x + v0.y * v0.y + v0.z * v0.z + v0.w * v0.w;
        ynacc += v1.x * v1.x + v1.y * v1.y + v1.z * v1.z + v1.w * v1.w;
        __nv_bfloat162 p0 = __floats2bfloat162_rn(v0.x, v0.y);
        __nv_bfloat162 p1 = __floats2bfloat162_rn(v0.z, v0.w);
        __nv_bfloat162 p2 = __floats2bfloat162_rn(v1.x, v1.y);
        __nv_bfloat162 p3 = __floats2bfloat162_rn(v1.z, v1.w);
        asm volatile("st.shared.v4.b32 [%0], {%1,%2,%3,%4};"
                     :: "r"(bdst + buf * B_STAGE_B),
                        "r"(*(uint32_t*)&p0), "r"(*(uint32_t*)&p1),
                        "r"(*(uint32_t*)&p2), "r"(*(uint32_t*)&p3));
    };

    // ldmatrix lane geometry (swizzled 128B rows)
    const uint32_t arow = lane & 15;
    const uint32_t arow128 = arow * 128;
    const uint32_t axor = (arow & 7) << 4;
    const uint32_t akse = (lane >> 4) * 16;
    const uint32_t brow_l = (lane & 7) + ((lane & 16) ? 8 : 0);
    const uint32_t brow128 = brow_l * 128;
    const uint32_t bxor = (brow_l & 7) << 4;
    const uint32_t bkse = (lane & 8) ? 16 : 0;

    // prologue: stages 0,1
    b_convert_store(bsrcf[0], bsrcf[1], 0);
    load_stage(0, 0);
    load_stage(1, 1);
    float4 fn0 = bsrcf[16], fn1 = bsrcf[17];

    for (int kc = 0; kc < CC / KC; kc++) {
        if (kc < CC / KC - 1)
            asm volatile("cp.async.wait_group 1;");
        else
            asm volatile("cp.async.wait_group 0;");
        __syncthreads();

        const int buf = kc & 1;
        const uint32_t abase = smA_u32 + buf * A_STAGE_B;
        const uint32_t bbase = smB_u32 + buf * B_STAGE_B;

#pragma unroll
        for (int ks = 0; ks < 4; ks++) {
            const uint32_t kbyte = ks * 32;
            uint32_t a[2][4];
#pragma unroll
            for (int si = 0; si < 2; si++) {
                if (si < nsl)
                    ldsm_x4(a[si][0], a[si][1], a[si][2], a[si][3],
                            abase + sp[si] * 2048 + arow128 + ((akse + kbyte) ^ axor));
            }
            const uint32_t baddr = bbase + brow128 + ((bkse + kbyte) ^ bxor);
#pragma unroll
            for (int g = 0; g < 4; g++) {             // B rows 16g..16g+15 ; tile = g>>1
                const bool gneed = (g < 2) ? need0 : need1;
                if (gneed) {
                    uint32_t b0, b1, b2, b3;
                    ldsm_x4(b0, b1, b2, b3, baddr + g * (16 * 128));
#pragma unroll
                    for (int si = 0; si < 2; si++) {
                        const bool use = (si < nsl) && ((g < 2) ? m0[si] : m1[si]);
                        if (use) {
                            mma16816(acc[si][2 * g], a[si][0], a[si][1], a[si][2], a[si][3], b0, b1);
                            mma16816(acc[si][2 * g + 1], a[si][0], a[si][1], a[si][2], a[si][3], b2, b3);
                        }
                    }
                }
            }
        }
        __syncthreads();
        if (kc + 1 < CC / KC) b_convert_store(fn0, fn1, (kc + 1) & 1);
        if (kc + 2 < CC / KC) {
            fn0 = bsrcf[(kc + 2) * 16];
            fn1 = bsrcf[(kc + 2) * 16 + 1];
            load_stage(kc + 2, buf);
        }
    }

    // ---- yn: reduce per-row sums (8 threads per row) ------------------------
    float ya = ynacc;
#pragma unroll
    for (int off = 4; off; off >>= 1) ya += __shfl_xor_sync(~0u, ya, off);
    if ((tid & 7) == 0) yn_s[brow] = ya;
    __syncthreads();

    // epilogue: min over applicable n-blocks per tile, atomicMin
#pragma unroll
    for (int si = 0; si < 2; si++) {
        if (si < nsl) {
            int p = sp[si];
            float xlo = xn_s[p * 16 + (lane >> 2)];
            float xhi = xn_s[p * 16 + 8 + (lane >> 2)];
            float mlo = 3.4e38f, mhi = 3.4e38f;
#pragma unroll
            for (int nb = 0; nb < 8; nb++) {
                if (nb < 4 ? m0[si] : m1[si]) {
                    int c0 = nb * 8 + ((lane & 3) << 1);
                    float y0 = yn_s[c0], y1 = yn_s[c0 + 1];
                    mlo = fminf(mlo, fminf(fmaf(-2.f, acc[si][nb][0], xlo) + y0,
                                           fmaf(-2.f, acc[si][nb][1], xlo) + y1));
                    mhi = fminf(mhi, fminf(fmaf(-2.f, acc[si][nb][2], xhi) + y0,
                                           fmaf(-2.f, acc[si][nb][3], xhi) + y1));
                }
            }
            mlo = fminf(mlo, __shfl_xor_sync(~0u, mlo, 1));
            mlo = fminf(mlo, __shfl_xor_sync(~0u, mlo, 2));
            mhi = fminf(mhi, __shfl_xor_sync(~0u, mhi, 1));
            mhi = fminf(mhi, __shfl_xor_sync(~0u, mhi, 2));
            if ((lane & 3) == 0) {
                int q = qoff_s[p];
                atomicMin((int*)&g_best[q + (lane >> 2)], __float_as_int(fmaxf(mlo, 0.f)));
                atomicMin((int*)&g_best[q + 8 + (lane >> 2)], __float_as_int(fmaxf(mhi, 0.f)));
            }
        }
    }
}

// ---------------- sqrt + per-b max (atomic) + pix56 transpose --------------
__global__ void k_finish(float* __restrict__ out) {
    __shared__ float red[14];
    const int b = blockIdx.x & 15;
    const int i = (blockIdx.x >> 4) * 448 + threadIdx.x;
    float v = sqrtf(g_best[i * BB + b]);
    g_pix56[b * (H1 * W1) + i] = v;
#pragma unroll
    for (int off = 16; off; off >>= 1) v = fmaxf(v, __shfl_xor_sync(~0u, v, off));
    if ((threadIdx.x & 31) == 0) red[threadIdx.x >> 5] = v;
    __syncthreads();
    if (threadIdx.x == 0) {
        float m = red[0];
#pragma unroll
        for (int w = 1; w < 14; w++) m = fmaxf(m, red[w]);
        atomicMax((int*)&out[b], __float_as_int(m));
    }
}

// ---------------- fused resize+blur: out = W * P * W^T ----------------------
__global__ void k_vres() {
    int idx = blockIdx.x * blockDim.x + threadIdx.x;
    if (idx >= BB * OH * H1) return;
    int x = idx % H1;
    int oy = (idx / H1) % OH;
    int b = idx / (OH * H1);
    const float* Wr = g_W + oy * H1;
    const float* P = g_pix56 + b * (H1 * W1) + x;
    float sum = 0.f;
#pragma unroll 8
    for (int k = 0; k < H1; k++) sum += Wr[k] * P[k * W1];
    g_tmp[idx] = sum;
}

__global__ void k_hres(float* __restrict__ out) {
    int idx = blockIdx.x * blockDim.x + threadIdx.x;
    if (idx >= BB * OH * OW) return;
    int ox = idx % OW;
    int row = idx / OW;
    const float* T = g_tmp + row * H1;
    const float* Wc = g_Wt + ox;
    float sum = 0.f;
#pragma unroll 8
    for (int k = 0; k < H1; k++) sum += T[k] * Wc[k * OH];
    out[idx] = sum;
}

// ---------------- launch ------------------------------------------------------
extern "C" void kernel_launch(void* const* d_in, const int* in_sizes, int n_in,
                              void* d_out, int out_size) {
    const float* emb = (const float*)d_in[0];
    const float* mem = (const float*)d_in[1];
    float* out = (float*)d_out;

    cudaFuncSetAttribute(k_dist, cudaFuncAttributeMaxDynamicSharedMemorySize, SM_TOT);

    k_convert_e<<<(H1 * W1 * BB + 7) / 8, 256>>>(emb, out);
    k_initW<<<1, 224>>>();
    k_dist<<<RH * (RW / 2), NTHR, SM_TOT>>>(mem);
    k_finish<<<BB * 7, 448>>>(out);                   // img -> out[0..15]
    k_vres<<<(BB * OH * H1 + 255) / 256, 256>>>();
    k_hres<<<(BB * OH * OW + 255) / 256, 256>>>(out + BB);  // blur -> out[16..]
}

// round 15
// speedup vs baseline: 1.2050x; 1.2050x over previous
#include <cuda_runtime.h>
#include <cuda_bf16.h>
#include <cstdint>
#include <math.h>

#define H1 56
#define W1 56
#define BB 16
#define NN 32
#define CC 512
#define RH 60
#define RW 60
#define OH 224
#define OW 224
#define KS 33
#define KC 64

// ---------------- scratch (device globals; no allocation allowed) ----------
__device__ __nv_bfloat16 g_Eb[H1 * W1 * BB * CC];     // 51.4 MB
__device__ float g_xn[H1 * W1 * BB];
__device__ float g_best[H1 * W1 * BB];                // min dsq, via atomicMin(int)
__device__ float g_pix56[BB * H1 * W1];
__device__ float g_tmp[BB * OH * H1];                 // W·P stage (16x224x56)
__device__ float g_W[OH * H1];                        // fused resize+blur matrix
__device__ float g_Wt[H1 * OH];                       // its transpose

// ---------------- fp32 -> bf16 conversion + norms + best/out init ----------
// Last block (blockIdx.x == gridDim.x-1) instead computes the fused W matrix.
__global__ void k_convert_e(const float* __restrict__ src, float* __restrict__ out) {
    if (blockIdx.x == gridDim.x - 1) {
        int i = threadIdx.x;                          // 224 of 256 threads active
        if (i < OH) {
            float gwv[KS], ssum = 0.f;
#pragma unroll
            for (int t = 0; t < KS; t++) {
                float x = (t - (KS - 1) / 2) * 0.25f;
                gwv[t] = expf(-0.5f * x * x);
                ssum += gwv[t];
            }
            float acc[H1];
#pragma unroll
            for (int k = 0; k < H1; k++) acc[k] = 0.f;
            for (int t = 0; t < KS; t++) {
                int yy = i + t - 16;
                yy = yy < 0 ? -yy : (yy > 223 ? 446 - yy : yy);   // reflect
                float uy = fminf(fmaxf((yy + 0.5f) * 0.25f - 0.5f, 0.f), 55.f);
                int y0 = (int)uy;
                float fy = uy - y0;
                int y1 = min(y0 + 1, H1 - 1);
                float g = gwv[t] / ssum;
                acc[y0] += g * (1.f - fy);
                acc[y1] += g * fy;
            }
            for (int k = 0; k < H1; k++) {
                g_W[i * H1 + k] = acc[k];
                g_Wt[k * OH + i] = acc[k];
            }
        }
        return;
    }

    int gi = blockIdx.x * blockDim.x + threadIdx.x;
    if (gi < H1 * W1 * BB) g_best[gi] = __int_as_float(0x7f800000);
    if (gi < BB) out[gi] = 0.f;

    int gw = gi >> 5;
    int lane = threadIdx.x & 31;
    if (gw >= H1 * W1 * BB) return;
    const float4* s = (const float4*)(src + (size_t)gw * CC);
    uint2* d = (uint2*)(g_Eb + (size_t)gw * CC);
    float acc = 0.f;
#pragma unroll
    for (int it = 0; it < 4; it++) {
        float4 v = s[it * 32 + lane];
        acc += v.x * v.x + v.y * v.y + v.z * v.z + v.w * v.w;
        __nv_bfloat162 lo = __floats2bfloat162_rn(v.x, v.y);
        __nv_bfloat162 hi = __floats2bfloat162_rn(v.z, v.w);
        uint2 o;
        o.x = *(uint32_t*)&lo;
        o.y = *(uint32_t*)&hi;
        d[it * 32 + lane] = o;
    }
#pragma unroll
    for (int off = 16; off; off >>= 1) acc += __shfl_xor_sync(~0u, acc, off);
    if (lane == 0) g_xn[gw] = acc;
}

// ---------------- main distance kernel: one CTA per PAIR of tiles ----------
__device__ __forceinline__ void mma16816(float* d, uint32_t a0, uint32_t a1,
                                         uint32_t a2, uint32_t a3,
                                         uint32_t b0, uint32_t b1) {
    asm volatile(
        "mma.sync.aligned.m16n8k16.row.col.f32.bf16.bf16.f32 "
        "{%0,%1,%2,%3}, {%4,%5,%6,%7}, {%8,%9}, {%0,%1,%2,%3};\n"
        : "+f"(d[0]), "+f"(d[1]), "+f"(d[2]), "+f"(d[3])
        : "r"(a0), "r"(a1), "r"(a2), "r"(a3), "r"(b0), "r"(b1));
}

__device__ __forceinline__ void ldsm_x4(uint32_t& r0, uint32_t& r1,
                                        uint32_t& r2, uint32_t& r3, uint32_t addr) {
    asm volatile("ldmatrix.sync.aligned.m8n8.x4.shared.b16 {%0,%1,%2,%3}, [%4];"
                 : "=r"(r0), "=r"(r1), "=r"(r2), "=r"(r3) : "r"(addr));
}

__device__ __forceinline__ void cp_async16(uint32_t dst, const void* src) {
    asm volatile("cp.async.cg.shared.global [%0], [%1], 16;" ::"r"(dst), "l"(src));
}

__device__ __forceinline__ uint32_t sw128(uint32_t off) {
    return off ^ ((off >> 3) & 0x70);
}

// smem layout (bytes), fused 2-tile version:
#define A_STAGE_B 61440
#define B_STAGE_B 8192
#define SM_A   0
#define SM_B   122880
#define SM_XN  139264          // 480 floats
#define SM_YN  141184          // 64 floats
#define SM_Q   141440          // 32 ints
#define SM_TOT 141568

#define NWARP 16
#define NTHR  512

__global__ void __launch_bounds__(NTHR, 1) k_dist(const float* __restrict__ mem) {
    extern __shared__ char smem[];
    float* xn_s = (float*)(smem + SM_XN);
    float* yn_s = (float*)(smem + SM_YN);
    int* qoff_s = (int*)(smem + SM_Q);
    const uint32_t sm_u32 = (uint32_t)__cvta_generic_to_shared(smem);
    const uint32_t smA_u32 = sm_u32 + SM_A;
    const uint32_t smB_u32 = sm_u32 + SM_B;

    const int r = blockIdx.x / (RW / 2);
    const int s0 = (blockIdx.x % (RW / 2)) * 2;
    const int t0 = r * RW + s0;                       // tiles t0, t0+1
    const int tid = threadIdx.x;
    const int wid = tid >> 5, lane = tid & 31;

    if (tid < 30) {
        int dh = tid / 6, dw = tid % 6;
        int h = r - 4 + dh, w = s0 - 4 + dw;
        qoff_s[tid] = (h >= 0 && h < H1 && w >= 0 && w < W1) ? (h * W1 + w) * BB : -1;
    }
    __syncthreads();
    if (tid < 480) {
        int q = qoff_s[tid >> 4];
        xn_s[tid] = (q >= 0) ? g_xn[q + (tid & 15)] : 0.f;
    }

    // warp's valid slots (warp-uniform): up to 2 (16 warps cover 30 slots)
    int sp[2];
    int nsl = 0;
#pragma unroll
    for (int p = wid; p < 30; p += NWARP)
        if (qoff_s[p] >= 0) sp[nsl++] = p;

    float acc[2][8][4];
#pragma unroll
    for (int a = 0; a < 2; a++)
#pragma unroll
        for (int g = 0; g < 8; g++)
#pragma unroll
            for (int c = 0; c < 4; c++) acc[a][g][c] = 0.f;

    // ---- hoisted A load addressing (480 rows, 8 slot-groups) ---------------
    const int seg = tid & 7;
    const int rowin = (tid >> 3) & 15;
    const int slot0 = tid >> 7;                       // 0..3
    const uint32_t adst0 = slot0 * 2048 + sw128(rowin * 128 + seg * 16);

    int aoffq[8];
#pragma unroll
    for (int i = 0; i < 8; i++) {
        int slot = slot0 + i * 4;
        int v = -1;
        if (slot < 30) {
            int q = qoff_s[slot];
            if (q >= 0) v = (q + rowin) * (CC / 8) + seg;
        }
        aoffq[i] = v;
    }
    const uint4* EbV = (const uint4*)g_Eb;

    auto load_stage = [&](int kc, int buf) {
        const uint32_t abase = smA_u32 + buf * A_STAGE_B + adst0;
        const int kadd = kc * 8;
#pragma unroll
        for (int i = 0; i < 8; i++) {
            if (aoffq[i] >= 0)
                cp_async16(abase + i * 8192, EbV + aoffq[i] + kadd);
        }
        asm volatile("cp.async.commit_group;");
    };

    // ---- B path: 64 rows fp32 -> bf16 (2 float4 per thread per stage) ------
    const int brow = tid >> 3;                        // 0..63
    const int j0 = (tid & 7) * 2;                     // even float4 index 0..14
    const float4* bsrcf =
        (const float4*)(mem + ((size_t)(t0 + (brow >> 5)) * NN + (brow & 31)) * CC) + j0;
    const uint32_t bdst = smB_u32 + sw128(brow * 128 + j0 * 8);
    float ynacc = 0.f;

    auto b_convert_store = [&](float4 v0, float4 v1, int buf) {
        ynacc += v0.x * v0.x + v0.y * v0.y + v0.z * v0.z + v0.w * v0.w;
        ynacc += v1.x * v1.x + v1.y * v1.y + v1.z * v1.z + v1.w * v1.w;
        __nv_bfloat162 p0 = __floats2bfloat162_rn(v0.x, v0.y);
        __nv_bfloat162 p1 = __floats2bfloat162_rn(v0.z, v0.w);
        __nv_bfloat162 p2 = __floats2bfloat162_rn(v1.x, v1.y);
        __nv_bfloat162 p3 = __floats2bfloat162_rn(v1.z, v1.w);
        asm volatile("st.shared.v4.b32 [%0], {%1,%2,%3,%4};"
                     :: "r"(bdst + buf * B_STAGE_B),
                        "r"(*(uint32_t*)&p0), "r"(*(uint32_t*)&p1),
                        "r"(*(uint32_t*)&p2), "r"(*(uint32_t*)&p3));
    };

    // ldmatrix lane geometry (swizzled 128B rows)
    const uint32_t arow = lane & 15;
    const uint32_t arow128 = arow * 128;
    const uint32_t axor = (arow & 7) << 4;
    const uint32_t akse = (lane >> 4) * 16;
    const uint32_t brow_l = (lane & 7) + ((lane & 16) ? 8 : 0);
    const uint32_t brow128 = brow_l * 128;
    const uint32_t bxor = (brow_l & 7) << 4;
    const uint32_t bkse = (lane & 8) ? 16 : 0;

    // prologue: stages 0,1
    b_convert_store(bsrcf[0], bsrcf[1], 0);
    load_stage(0, 0);
    load_stage(1, 1);
    float4 fn0 = bsrcf[16], fn1 = bsrcf[17];

    for (int kc = 0; kc < CC / KC; kc++) {
        if (kc < CC / KC - 1)
            asm volatile("cp.async.wait_group 1;");
        else
            asm volatile("cp.async.wait_group 0;");
        __syncthreads();

        const int buf = kc & 1;
        const uint32_t abase = smA_u32 + buf * A_STAGE_B;
        const uint32_t bbase = smB_u32 + buf * B_STAGE_B;

#pragma unroll
        for (int ks = 0; ks < 4; ks++) {
            const uint32_t kbyte = ks * 32;
            uint32_t a[2][4];
#pragma unroll
            for (int si = 0; si < 2; si++) {
                if (si < nsl)
                    ldsm_x4(a[si][0], a[si][1], a[si][2], a[si][3],
                            abase + sp[si] * 2048 + arow128 + ((akse + kbyte) ^ axor));
            }
            const uint32_t baddr = bbase + brow128 + ((bkse + kbyte) ^ bxor);
#pragma unroll
            for (int g = 0; g < 4; g++) {             // B rows 16g..16g+15
                uint32_t b0, b1, b2, b3;
                ldsm_x4(b0, b1, b2, b3, baddr + g * (16 * 128));
#pragma unroll
                for (int si = 0; si < 2; si++) {
                    if (si < nsl) {
                        mma16816(acc[si][2 * g], a[si][0], a[si][1], a[si][2], a[si][3], b0, b1);
                        mma16816(acc[si][2 * g + 1], a[si][0], a[si][1], a[si][2], a[si][3], b2, b3);
                    }
                }
            }
        }
        __syncthreads();
        if (kc + 1 < CC / KC) b_convert_store(fn0, fn1, (kc + 1) & 1);
        if (kc + 2 < CC / KC) {
            fn0 = bsrcf[(kc + 2) * 16];
            fn1 = bsrcf[(kc + 2) * 16 + 1];
            load_stage(kc + 2, buf);
        }
    }

    // ---- yn: reduce per-row sums (8 threads per row) ------------------------
    float ya = ynacc;
#pragma unroll
    for (int off = 4; off; off >>= 1) ya += __shfl_xor_sync(~0u, ya, off);
    if ((tid & 7) == 0) yn_s[brow] = ya;
    __syncthreads();

    // epilogue: min over applicable n-blocks per tile, atomicMin
#pragma unroll
    for (int si = 0; si < 2; si++) {
        if (si < nsl) {
            int p = sp[si];
            int dw = p % 6;
            bool m0 = (dw <= 4), m1 = (dw >= 1);      // tile0 / tile1 validity
            float xlo = xn_s[p * 16 + (lane >> 2)];
            float xhi = xn_s[p * 16 + 8 + (lane >> 2)];
            float mlo = 3.4e38f, mhi = 3.4e38f;
#pragma unroll
            for (int nb = 0; nb < 8; nb++) {
                if (nb < 4 ? m0 : m1) {
                    int c0 = nb * 8 + ((lane & 3) << 1);
                    float y0 = yn_s[c0], y1 = yn_s[c0 + 1];
                    mlo = fminf(mlo, fminf(fmaf(-2.f, acc[si][nb][0], xlo) + y0,
                                           fmaf(-2.f, acc[si][nb][1], xlo) + y1));
                    mhi = fminf(mhi, fminf(fmaf(-2.f, acc[si][nb][2], xhi) + y0,
                                           fmaf(-2.f, acc[si][nb][3], xhi) + y1));
                }
            }
            mlo = fminf(mlo, __shfl_xor_sync(~0u, mlo, 1));
            mlo = fminf(mlo, __shfl_xor_sync(~0u, mlo, 2));
            mhi = fminf(mhi, __shfl_xor_sync(~0u, mhi, 1));
            mhi = fminf(mhi, __shfl_xor_sync(~0u, mhi, 2));
            if ((lane & 3) == 0) {
                int q = qoff_s[p];
                atomicMin((int*)&g_best[q + (lane >> 2)], __float_as_int(fmaxf(mlo, 0.f)));
                atomicMin((int*)&g_best[q + 8 + (lane >> 2)], __float_as_int(fmaxf(mhi, 0.f)));
            }
        }
    }
}

// ---------------- sqrt + per-b max (atomic) + pix56 transpose --------------
__global__ void k_finish(float* __restrict__ out) {
    __shared__ float red[14];
    const int b = blockIdx.x & 15;
    const int i = (blockIdx.x >> 4) * 448 + threadIdx.x;
    float v = sqrtf(g_best[i * BB + b]);
    g_pix56[b * (H1 * W1) + i] = v;
#pragma unroll
    for (int off = 16; off; off >>= 1) v = fmaxf(v, __shfl_xor_sync(~0u, v, off));
    if ((threadIdx.x & 31) == 0) red[threadIdx.x >> 5] = v;
    __syncthreads();
    if (threadIdx.x == 0) {
        float m = red[0];
#pragma unroll
        for (int w = 1; w < 14; w++) m = fmaxf(m, red[w]);
        atomicMax((int*)&out[b], __float_as_int(m));
    }
}

// ---------------- fused resize+blur: out = W * P * W^T ----------------------
__global__ void k_vres() {
    int idx = blockIdx.x * blockDim.x + threadIdx.x;
    if (idx >= BB * OH * H1) return;
    int x = idx % H1;
    int oy = (idx / H1) % OH;
    int b = idx / (OH * H1);
    const float* Wr = g_W + oy * H1;
    const float* P = g_pix56 + b * (H1 * W1) + x;
    float sum = 0.f;
#pragma unroll 8
    for (int k = 0; k < H1; k++) sum += Wr[k] * P[k * W1];
    g_tmp[idx] = sum;
}

__global__ void k_hres(float* __restrict__ out) {
    int idx = blockIdx.x * blockDim.x + threadIdx.x;
    if (idx >= BB * OH * OW) return;
    int ox = idx % OW;
    int row = idx / OW;
    const float* T = g_tmp + row * H1;
    const float* Wc = g_Wt + ox;
    float sum = 0.f;
#pragma unroll 8
    for (int k = 0; k < H1; k++) sum += T[k] * Wc[k * OH];
    out[idx] = sum;
}

// ---------------- launch ------------------------------------------------------
extern "C" void kernel_launch(void* const* d_in, const int* in_sizes, int n_in,
                              void* d_out, int out_size) {
    const float* emb = (const float*)d_in[0];
    const float* mem = (const float*)d_in[1];
    float* out = (float*)d_out;

    cudaFuncSetAttribute(k_dist, cudaFuncAttributeMaxDynamicSharedMemorySize, SM_TOT);

    // +1 block: last block computes the fused W matrix (was k_initW)
    k_convert_e<<<(H1 * W1 * BB + 7) / 8 + 1, 256>>>(emb, out);
    k_dist<<<RH * (RW / 2), NTHR, SM_TOT>>>(mem);
    k_finish<<<BB * 7, 448>>>(out);                   // img -> out[0..15]
    k_vres<<<(BB * OH * H1 + 255) / 256, 256>>>();
    k_hres<<<(BB * OH * OW + 255) / 256, 256>>>(out + BB);  // blur -> out[16..]
}